// round 14
// baseline (speedup 1.0000x reference)
#include <cuda_runtime.h>
#include <cuda_bf16.h>
#include <cuda_fp16.h>
#include <stdint.h>
#include <math.h>

#define BATCH 2
#define SEQ   2048
#define EMB   1024
#define HEADS 16
#define HDIM  64
#define MROWS (BATCH*SEQ)   /* 4096 */
#define QKVN  (3*EMB)       /* 3072 */
#define KDIM  EMB

#define QSCALE  0.02209708691207961f
#define QSCALE2 (QSCALE * 1.4426950408889634f)
#define SKIP_T  25.0f

// ---------------- scratch ----------------
__device__ __align__(256) __nv_bfloat16 g_xh [(size_t)MROWS*EMB];
__device__ __align__(256) __nv_bfloat16 g_xl [(size_t)MROWS*EMB];
__device__ __align__(256) __half        g_xf [(size_t)MROWS*EMB];
__device__ __align__(256) __nv_bfloat16 g_Bqh[(size_t)2*EMB*EMB];
__device__ __align__(256) __nv_bfloat16 g_Bql[(size_t)2*EMB*EMB];
__device__ __align__(256) __half        g_Bvf[(size_t)EMB*EMB];
__device__ __align__(256) __half        g_Bof[(size_t)EMB*EMB];
__device__ __align__(256) __nv_bfloat16 g_QKVh[(size_t)MROWS*QKVN];  /* V region = fp16 bits */
__device__ __align__(256) __nv_bfloat16 g_QKVl[(size_t)MROWS*QKVN];
__device__ __align__(256) __half        g_At [(size_t)MROWS*EMB];

// ---------------- helpers ----------------
__device__ __forceinline__ uint32_t cvta_smem(const void* p) {
    uint32_t a;
    asm("{ .reg .u64 t; cvta.to.shared.u64 t, %1; cvt.u32.u64 %0, t; }" : "=r"(a) : "l"(p));
    return a;
}
__device__ __forceinline__ void cp16(uint32_t dst, const void* src) {
    asm volatile("cp.async.cg.shared.global [%0], [%1], 16;" :: "r"(dst), "l"(src));
}
#define CP_COMMIT() asm volatile("cp.async.commit_group;" ::: "memory")
#define CP_WAIT2()  asm volatile("cp.async.wait_group 2;" ::: "memory")
#define CP_WAIT1()  asm volatile("cp.async.wait_group 1;" ::: "memory")
#define CP_WAIT0()  asm volatile("cp.async.wait_group 0;" ::: "memory")

__device__ __forceinline__ void ldsm4(uint32_t& r0, uint32_t& r1, uint32_t& r2, uint32_t& r3,
                                      uint32_t addr) {
    asm volatile("ldmatrix.sync.aligned.m8n8.x4.shared.b16 {%0,%1,%2,%3},[%4];"
                 : "=r"(r0), "=r"(r1), "=r"(r2), "=r"(r3) : "r"(addr));
}
__device__ __forceinline__ void ldsm4t(uint32_t& r0, uint32_t& r1, uint32_t& r2, uint32_t& r3,
                                       uint32_t addr) {
    asm volatile("ldmatrix.sync.aligned.m8n8.x4.trans.shared.b16 {%0,%1,%2,%3},[%4];"
                 : "=r"(r0), "=r"(r1), "=r"(r2), "=r"(r3) : "r"(addr));
}
__device__ __forceinline__ void mma_bf(float c[4], const uint32_t a[4], uint32_t b0, uint32_t b1) {
    asm("mma.sync.aligned.m16n8k16.row.col.f32.bf16.bf16.f32 "
        "{%0,%1,%2,%3}, {%4,%5,%6,%7}, {%8,%9}, {%0,%1,%2,%3};"
        : "+f"(c[0]), "+f"(c[1]), "+f"(c[2]), "+f"(c[3])
        : "r"(a[0]), "r"(a[1]), "r"(a[2]), "r"(a[3]), "r"(b0), "r"(b1));
}
__device__ __forceinline__ void mma_hf(float c[4], const uint32_t a[4], uint32_t b0, uint32_t b1) {
    asm("mma.sync.aligned.m16n8k16.row.col.f32.f16.f16.f32 "
        "{%0,%1,%2,%3}, {%4,%5,%6,%7}, {%8,%9}, {%0,%1,%2,%3};"
        : "+f"(c[0]), "+f"(c[1]), "+f"(c[2]), "+f"(c[3])
        : "r"(a[0]), "r"(a[1]), "r"(a[2]), "r"(a[3]), "r"(b0), "r"(b1));
}
__device__ __forceinline__ float ex2(float x) {
    float r;
    asm("ex2.approx.ftz.f32 %0, %1;" : "=f"(r) : "f"(x));
    return r;
}
__device__ __forceinline__ uint32_t ex2_h2(float x, float y) {
    uint32_t h, r;
    asm("cvt.rn.f16x2.f32 %0, %1, %2;" : "=r"(h) : "f"(y), "f"(x));
    asm("ex2.approx.f16x2 %0, %1;" : "=r"(r) : "r"(h));
    return r;
}
__device__ __forceinline__ uint32_t packbf(float x, float y) {
    __nv_bfloat162 t = __floats2bfloat162_rn(x, y);
    return *reinterpret_cast<uint32_t*>(&t);
}
__device__ __forceinline__ uint32_t packres(float x, float y, uint32_t h) {
    __nv_bfloat162 hh = *reinterpret_cast<__nv_bfloat162*>(&h);
    return packbf(x - __bfloat162float(hh.x), y - __bfloat162float(hh.y));
}
__device__ __forceinline__ uint32_t packh(float x, float y) {
    __half2 t = __floats2half2_rn(x, y);
    return *reinterpret_cast<uint32_t*>(&t);
}
__device__ __forceinline__ void split2(float v, __nv_bfloat16& hi, __nv_bfloat16& lo) {
    hi = __float2bfloat16(v);
    lo = __float2bfloat16(v - __bfloat162float(hi));
}

// ---------------- packing kernels ----------------
__global__ void split_x(const float* __restrict__ x, __nv_bfloat16* __restrict__ hi,
                        __nv_bfloat16* __restrict__ lo, __half* __restrict__ hf, int n) {
    int i = blockIdx.x * blockDim.x + threadIdx.x;
    if (i >= n) return;
    float v = x[i];
    split2(v, hi[i], lo[i]);
    hf[i] = __float2half(v);
}

__global__ void pack_qkv_t(const float* __restrict__ Wq, const float* __restrict__ Wk,
                           const float* __restrict__ Wv,
                           __nv_bfloat16* __restrict__ hi, __nv_bfloat16* __restrict__ lo,
                           __half* __restrict__ vf) {
    __shared__ float ts[64][65];
    const int tid = threadIdx.x;
    const int kb = blockIdx.x, hid = blockIdx.y, wh = blockIdx.z;
    const float* src = (wh == 0) ? Wq : (wh == 1) ? Wk : Wv;
    const float sc = (wh == 0) ? QSCALE2 : 1.0f;

#pragma unroll
    for (int p = 0; p < 16; p++) {
        int kr = (tid >> 6) + p * 4;
        int i  = tid & 63;
        ts[kr][i] = src[(size_t)hid * (EMB * HDIM) + (size_t)(kb * 64 + kr) * HDIM + i];
    }
    __syncthreads();
#pragma unroll
    for (int p = 0; p < 16; p++) {
        int i = (tid >> 6) + p * 4;
        int k = tid & 63;
        float v = ts[k][i] * sc;
        if (wh == 2) {
            size_t o = ((size_t)(hid * 64 + i) << 10) + kb * 64 + k;
            vf[o] = __float2half(v);
        } else {
            size_t o = ((size_t)(wh * 1024 + hid * 64 + i) << 10) + kb * 64 + k;
            split2(v, hi[o], lo[o]);
        }
    }
}

__global__ void pack_wo(const float* __restrict__ Wo, __half* __restrict__ hf) {
    int idx = blockIdx.x * blockDim.x + threadIdx.x;
    if (idx >= EMB * EMB) return;
    hf[idx] = __float2half(Wo[idx]);
}

// ---------------- merged projection: QK (bf16 3-pass) + V (fp16 1-pass) ----------------
#define GTILE  8192
#define GSTAGE 32768
#define GVSTAGE 16384
#define GNC    (KDIM/32)

__global__ __launch_bounds__(256, 2)
void gemm_proj(const __nv_bfloat16* __restrict__ Ah, const __nv_bfloat16* __restrict__ Al,
               const __nv_bfloat16* __restrict__ Bh, const __nv_bfloat16* __restrict__ Bl,
               __nv_bfloat16* __restrict__ Ch, __nv_bfloat16* __restrict__ Cl,
               const __half* __restrict__ Af, const __half* __restrict__ Bvf,
               __half* __restrict__ Cv) {
    extern __shared__ __align__(16) char smraw[];
    uint32_t smb = cvta_smem(smraw);
    const int tid = threadIdx.x, lane = tid & 31, wid = tid >> 5;
    const int wm = wid & 3, wn = wid >> 2;
    const int mb = blockIdx.y;
    const int grp = lane >> 2, qr = lane & 3;

    float acc[2][8][4];
#pragma unroll
    for (int a = 0; a < 2; a++)
#pragma unroll
        for (int b = 0; b < 8; b++)
#pragma unroll
            for (int c = 0; c < 4; c++) acc[a][b][c] = 0.f;

    if (blockIdx.x < 16) {
        // ---------- QK path: bf16 3-pass, 3-stage ----------
        const int nb = blockIdx.x;
        const __nv_bfloat16* gsrc[4] = {
            Ah + (size_t)mb * 128 * KDIM, Al + (size_t)mb * 128 * KDIM,
            Bh + (size_t)nb * 128 * KDIM, Bl + (size_t)nb * 128 * KDIM };

        auto ldchunk = [&](int buf, int ck) {
            uint32_t bb = smb + buf * GSTAGE;
#pragma unroll
            for (int q = 0; q < 8; q++) {
                int i = q * 256 + tid;
                int t = i >> 9;
                int r = (i >> 2) & 127;
                int c16 = i & 3;
                uint32_t dst = bb + t * GTILE + r * 64 + ((c16 ^ ((r >> 1) & 3)) << 4);
                cp16(dst, gsrc[t] + (size_t)r * KDIM + ck * 32 + c16 * 8);
            }
        };

        ldchunk(0, 0); CP_COMMIT();
        ldchunk(1, 1); CP_COMMIT();

        int buf = 0, rb = 2;
        for (int c = 0; c < GNC; c++) {
            if (c + 1 < GNC) CP_WAIT1(); else CP_WAIT0();
            __syncthreads();
            if (c + 2 < GNC) {
                ldchunk(rb, c + 2); CP_COMMIT();
                rb = (rb == 2) ? 0 : rb + 1;
            }
            uint32_t bb = smb + buf * GSTAGE;

#pragma unroll
            for (int s = 0; s < 2; s++) {
                uint32_t ah[2][4], al[2][4];
#pragma unroll
                for (int mt = 0; mt < 2; mt++) {
                    uint32_t row = 32 * wm + 16 * mt + ((lane >> 3) & 1) * 8 + (lane & 7);
                    uint32_t kb  = (lane >> 4) * 16 + s * 32;
                    uint32_t ad  = bb + row * 64 + ((((kb >> 4)) ^ ((row >> 1) & 3)) << 4);
                    ldsm4(ah[mt][0], ah[mt][1], ah[mt][2], ah[mt][3], ad);
                    ldsm4(al[mt][0], al[mt][1], al[mt][2], al[mt][3], ad + GTILE);
                }
#pragma unroll
                for (int np = 0; np < 4; np++) {
                    uint32_t row = 64 * wn + 16 * np + ((lane >> 4) & 1) * 8 + (lane & 7);
                    uint32_t kb  = ((lane >> 3) & 1) * 16 + s * 32;
                    uint32_t bd  = bb + 2 * GTILE + row * 64 + ((((kb >> 4)) ^ ((row >> 1) & 3)) << 4);
                    uint32_t bh0, bh1, bh2, bh3, bl0, bl1, bl2, bl3;
                    ldsm4(bh0, bh1, bh2, bh3, bd);
                    ldsm4(bl0, bl1, bl2, bl3, bd + GTILE);
#pragma unroll
                    for (int p = 0; p < 3; p++) {
                        const uint32_t* a0 = (p == 1) ? al[0] : ah[0];
                        const uint32_t* a1 = (p == 1) ? al[1] : ah[1];
                        uint32_t c0 = (p == 2) ? bl0 : bh0, c1 = (p == 2) ? bl1 : bh1;
                        uint32_t c2 = (p == 2) ? bl2 : bh2, c3 = (p == 2) ? bl3 : bh3;
                        mma_bf(acc[0][2 * np],     a0, c0, c1);
                        mma_bf(acc[1][2 * np],     a1, c0, c1);
                        mma_bf(acc[0][2 * np + 1], a0, c2, c3);
                        mma_bf(acc[1][2 * np + 1], a1, c2, c3);
                    }
                }
            }
            buf = (buf == 2) ? 0 : buf + 1;
        }

#pragma unroll
        for (int mt = 0; mt < 2; mt++) {
            size_t r0 = (size_t)mb * 128 + 32 * wm + 16 * mt + grp;
#pragma unroll
            for (int nt = 0; nt < 8; nt++) {
                int col = nb * 128 + 64 * wn + 8 * nt + 2 * qr;
                float* c4 = acc[mt][nt];
                uint32_t h0 = packbf(c4[0], c4[1]), l0 = packres(c4[0], c4[1], h0);
                uint32_t h1 = packbf(c4[2], c4[3]), l1 = packres(c4[2], c4[3], h1);
                *(uint32_t*)&Ch[r0 * QKVN + col]       = h0;
                *(uint32_t*)&Cl[r0 * QKVN + col]       = l0;
                *(uint32_t*)&Ch[(r0 + 8) * QKVN + col] = h1;
                *(uint32_t*)&Cl[(r0 + 8) * QKVN + col] = l1;
            }
        }
    } else {
        // ---------- V path: fp16 1-pass, 4-stage ----------
        const int nb = blockIdx.x - 16;
        const __half* gsrc[2] = { Af + (size_t)mb * 128 * KDIM, Bvf + (size_t)nb * 128 * KDIM };

        auto ldchunk = [&](int buf, int ck) {
            uint32_t bb = smb + buf * GVSTAGE;
#pragma unroll
            for (int q = 0; q < 4; q++) {
                int i = q * 256 + tid;
                int t = i >> 9;
                int r = (i >> 2) & 127;
                int c16 = i & 3;
                uint32_t dst = bb + t * GTILE + r * 64 + ((c16 ^ ((r >> 1) & 3)) << 4);
                cp16(dst, gsrc[t] + (size_t)r * KDIM + ck * 32 + c16 * 8);
            }
        };

        ldchunk(0, 0); CP_COMMIT();
        ldchunk(1, 1); CP_COMMIT();
        ldchunk(2, 2); CP_COMMIT();

        int rb = 3;
        for (int c = 0; c < GNC; c++) {
            int rem = GNC - c;
            if (rem >= 3) CP_WAIT2(); else if (rem == 2) CP_WAIT1(); else CP_WAIT0();
            __syncthreads();
            if (c + 3 < GNC) {
                ldchunk(rb, c + 3); CP_COMMIT();
                rb = (rb + 1) & 3;
            }
            uint32_t bb = smb + (c & 3) * GVSTAGE;

#pragma unroll
            for (int s = 0; s < 2; s++) {
                uint32_t ah[2][4];
#pragma unroll
                for (int mt = 0; mt < 2; mt++) {
                    uint32_t row = 32 * wm + 16 * mt + ((lane >> 3) & 1) * 8 + (lane & 7);
                    uint32_t kb  = (lane >> 4) * 16 + s * 32;
                    uint32_t ad  = bb + row * 64 + ((((kb >> 4)) ^ ((row >> 1) & 3)) << 4);
                    ldsm4(ah[mt][0], ah[mt][1], ah[mt][2], ah[mt][3], ad);
                }
#pragma unroll
                for (int np = 0; np < 4; np++) {
                    uint32_t row = 64 * wn + 16 * np + ((lane >> 4) & 1) * 8 + (lane & 7);
                    uint32_t kb  = ((lane >> 3) & 1) * 16 + s * 32;
                    uint32_t bd  = bb + GTILE + row * 64 + ((((kb >> 4)) ^ ((row >> 1) & 3)) << 4);
                    uint32_t b0, b1, b2, b3;
                    ldsm4(b0, b1, b2, b3, bd);
                    mma_hf(acc[0][2 * np],     ah[0], b0, b1);
                    mma_hf(acc[1][2 * np],     ah[1], b0, b1);
                    mma_hf(acc[0][2 * np + 1], ah[0], b2, b3);
                    mma_hf(acc[1][2 * np + 1], ah[1], b2, b3);
                }
            }
        }

#pragma unroll
        for (int mt = 0; mt < 2; mt++) {
            size_t r0 = (size_t)mb * 128 + 32 * wm + 16 * mt + grp;
#pragma unroll
            for (int nt = 0; nt < 8; nt++) {
                int col = nb * 128 + 64 * wn + 8 * nt + 2 * qr;
                float* c4 = acc[mt][nt];
                *(uint32_t*)&Cv[r0 * QKVN + col]       = packh(c4[0], c4[1]);
                *(uint32_t*)&Cv[(r0 + 8) * QKVN + col] = packh(c4[2], c4[3]);
            }
        }
    }
}

// ---------------- GEMM-O: fp16 1-pass, 4-stage ----------------
#define GOSTAGE 16384

__global__ __launch_bounds__(256, 2)
void gemm_o(const __half* __restrict__ A, const __half* __restrict__ B,
            float* __restrict__ C, int N) {
    extern __shared__ __align__(16) char smraw[];
    uint32_t smb = cvta_smem(smraw);
    const int tid = threadIdx.x, lane = tid & 31, wid = tid >> 5;
    const int wm = wid & 3, wn = wid >> 2;
    const int nb = blockIdx.x, mb = blockIdx.y;

    const __half* gsrc[2] = { A + (size_t)mb * 128 * KDIM, B + (size_t)nb * 128 * KDIM };

    auto ldchunk = [&](int buf, int ck) {
        uint32_t bb = smb + buf * GOSTAGE;
#pragma unroll
        for (int q = 0; q < 4; q++) {
            int i = q * 256 + tid;
            int t = i >> 9;
            int r = (i >> 2) & 127;
            int c16 = i & 3;
            uint32_t dst = bb + t * GTILE + r * 64 + ((c16 ^ ((r >> 1) & 3)) << 4);
            cp16(dst, gsrc[t] + (size_t)r * KDIM + ck * 32 + c16 * 8);
        }
    };

    ldchunk(0, 0); CP_COMMIT();
    ldchunk(1, 1); CP_COMMIT();
    ldchunk(2, 2); CP_COMMIT();

    float acc[2][8][4];
#pragma unroll
    for (int a = 0; a < 2; a++)
#pragma unroll
        for (int b = 0; b < 8; b++)
#pragma unroll
            for (int c = 0; c < 4; c++) acc[a][b][c] = 0.f;

    int rb = 3;
    for (int c = 0; c < GNC; c++) {
        int rem = GNC - c;
        if (rem >= 3) CP_WAIT2(); else if (rem == 2) CP_WAIT1(); else CP_WAIT0();
        __syncthreads();
        if (c + 3 < GNC) {
            ldchunk(rb, c + 3); CP_COMMIT();
            rb = (rb + 1) & 3;
        }
        uint32_t bb = smb + (c & 3) * GOSTAGE;

#pragma unroll
        for (int s = 0; s < 2; s++) {
            uint32_t ah[2][4];
#pragma unroll
            for (int mt = 0; mt < 2; mt++) {
                uint32_t row = 32 * wm + 16 * mt + ((lane >> 3) & 1) * 8 + (lane & 7);
                uint32_t kb  = (lane >> 4) * 16 + s * 32;
                uint32_t ad  = bb + row * 64 + ((((kb >> 4)) ^ ((row >> 1) & 3)) << 4);
                ldsm4(ah[mt][0], ah[mt][1], ah[mt][2], ah[mt][3], ad);
            }
#pragma unroll
            for (int np = 0; np < 4; np++) {
                uint32_t row = 64 * wn + 16 * np + ((lane >> 4) & 1) * 8 + (lane & 7);
                uint32_t kb  = ((lane >> 3) & 1) * 16 + s * 32;
                uint32_t bd  = bb + GTILE + row * 64 + ((((kb >> 4)) ^ ((row >> 1) & 3)) << 4);
                uint32_t b0, b1, b2, b3;
                ldsm4(b0, b1, b2, b3, bd);
                mma_hf(acc[0][2 * np],     ah[0], b0, b1);
                mma_hf(acc[1][2 * np],     ah[1], b0, b1);
                mma_hf(acc[0][2 * np + 1], ah[0], b2, b3);
                mma_hf(acc[1][2 * np + 1], ah[1], b2, b3);
            }
        }
    }

    const int grp = lane >> 2, qr = lane & 3;
#pragma unroll
    for (int mt = 0; mt < 2; mt++) {
        size_t r0 = (size_t)mb * 128 + 32 * wm + 16 * mt + grp;
#pragma unroll
        for (int nt = 0; nt < 8; nt++) {
            int col = nb * 128 + 64 * wn + 8 * nt + 2 * qr;
            float* c4 = acc[mt][nt];
            *(float2*)&C[r0 * N + col]       = make_float2(c4[0], c4[1]);
            *(float2*)&C[(r0 + 8) * N + col] = make_float2(c4[2], c4[3]);
        }
    }
}

// ---------------- Flash attention: fp16x2 softmax + MMA l-sum ----------------
#define FPITCH 144
#define FTILE  9216
#define FSTAGE 27648
#define NKT    (SEQ/64)
#define ONES2  0x3C003C00u

__global__ __launch_bounds__(256, 2)
void flash_mma(const __nv_bfloat16* __restrict__ Qh, const __nv_bfloat16* __restrict__ Ql,
               __half* __restrict__ Out) {
    extern __shared__ __align__(16) char smraw[];
    uint32_t smb = cvta_smem(smraw);

    const int tid = threadIdx.x, lane = tid & 31, w = tid >> 5;
    const int grp = lane >> 2, qr = lane & 3;
    const int qt = blockIdx.x, h = blockIdx.y, b = blockIdx.z;

    const size_t batch_row = (size_t)b * SEQ;

    const __nv_bfloat16* kvsrc[3] = {
        Qh + batch_row * QKVN + EMB + h * HDIM,
        Ql + batch_row * QKVN + EMB + h * HDIM,
        Qh + batch_row * QKVN + 2 * EMB + h * HDIM };

    auto ldtile = [&](int bf, int kt) {
        uint32_t bb = smb + bf * FSTAGE;
        size_t rbase = (size_t)kt * 64;
#pragma unroll
        for (int q = 0; q < 6; q++) {
            int i = q * 256 + tid;
            int t = i >> 9;
            int r = (i >> 3) & 63;
            int sg = i & 7;
            cp16(bb + t * FTILE + r * FPITCH + sg * 16,
                 kvsrc[t] + (rbase + r) * QKVN + sg * 8);
        }
    };

    uint32_t qh[4][4], ql[4][4];
    {
        size_t r0 = batch_row + (size_t)qt * 128 + w * 16 + grp;
        const __nv_bfloat16* qb_h = Qh + r0 * QKVN + h * HDIM;
        const __nv_bfloat16* qb_l = Ql + r0 * QKVN + h * HDIM;
#pragma unroll
        for (int t = 0; t < 4; t++) {
            int c0 = t * 16 + 2 * qr;
            qh[t][0] = *(const uint32_t*)(qb_h + c0);
            qh[t][1] = *(const uint32_t*)(qb_h + 8 * QKVN + c0);
            qh[t][2] = *(const uint32_t*)(qb_h + c0 + 8);
            qh[t][3] = *(const uint32_t*)(qb_h + 8 * QKVN + c0 + 8);
            ql[t][0] = *(const uint32_t*)(qb_l + c0);
            ql[t][1] = *(const uint32_t*)(qb_l + 8 * QKVN + c0);
            ql[t][2] = *(const uint32_t*)(qb_l + c0 + 8);
            ql[t][3] = *(const uint32_t*)(qb_l + 8 * QKVN + c0 + 8);
        }
    }

    float o[8][4];
#pragma unroll
    for (int j = 0; j < 8; j++)
#pragma unroll
        for (int c = 0; c < 4; c++) o[j][c] = 0.f;
    float lacc[4] = {0.f, 0.f, 0.f, 0.f};
    float m0 = -1e30f, m1 = -1e30f;

    ldtile(0, 0); CP_COMMIT();
    ldtile(1, 1); CP_COMMIT();
    ldtile(2, 2); CP_COMMIT();

    int rb = 3;
    for (int kt = 0; kt < NKT; kt++) {
        int rem = NKT - kt;
        if (rem >= 3) CP_WAIT2(); else if (rem == 2) CP_WAIT1(); else CP_WAIT0();
        __syncthreads();
        if (kt + 3 < NKT) {
            ldtile(rb, kt + 3); CP_COMMIT();
            rb = (rb + 1) & 3;
        }
        uint32_t sb  = smb + (kt & 3) * FSTAGE;
        uint32_t khb = sb, vhb = sb + 2 * FTILE;

        // ---- S = Q K^T (16 x 64 per warp), bf16 3-pass ----
        float s[8][4];
#pragma unroll
        for (int j = 0; j < 8; j++) {
            uint32_t ka = khb + (8 * j + (lane & 7)) * FPITCH + (lane >> 3) * 16;
            uint32_t la = ka + FTILE;
            uint32_t h0, h1, h2, h3, h4, h5, h6, h7;
            uint32_t e0, e1, e2, e3, e4, e5, e6, e7;
            ldsm4(h0, h1, h2, h3, ka);
            ldsm4(h4, h5, h6, h7, ka + 64);
            ldsm4(e0, e1, e2, e3, la);
            ldsm4(e4, e5, e6, e7, la + 64);
            s[j][0] = s[j][1] = s[j][2] = s[j][3] = 0.f;
            mma_bf(s[j], qh[0], h0, h1); mma_bf(s[j], ql[0], h0, h1); mma_bf(s[j], qh[0], e0, e1);
            mma_bf(s[j], qh[1], h2, h3); mma_bf(s[j], ql[1], h2, h3); mma_bf(s[j], qh[1], e2, e3);
            mma_bf(s[j], qh[2], h4, h5); mma_bf(s[j], ql[2], h4, h5); mma_bf(s[j], qh[2], e4, e5);
            mma_bf(s[j], qh[3], h6, h7); mma_bf(s[j], ql[3], h6, h7); mma_bf(s[j], qh[3], e6, e7);
        }

        // ---- maxima (quad-reduced) ----
        float t0 = -1e30f, t1 = -1e30f;
#pragma unroll
        for (int j = 0; j < 8; j++) {
            t0 = fmaxf(t0, fmaxf(s[j][0], s[j][1]));
            t1 = fmaxf(t1, fmaxf(s[j][2], s[j][3]));
        }
        t0 = fmaxf(t0, __shfl_xor_sync(0xffffffffu, t0, 1));
        t0 = fmaxf(t0, __shfl_xor_sync(0xffffffffu, t0, 2));
        t1 = fmaxf(t1, __shfl_xor_sync(0xffffffffu, t1, 1));
        t1 = fmaxf(t1, __shfl_xor_sync(0xffffffffu, t1, 2));

        bool negl = (t0 < m0 - SKIP_T) && (t1 < m1 - SKIP_T);
        if (__all_sync(0xffffffffu, negl)) continue;

        bool newmax = (t0 > m0) || (t1 > m1);
        if (newmax) {
            float n0 = fmaxf(m0, t0), n1 = fmaxf(m1, t1);
            float a0 = ex2(m0 - n0), a1 = ex2(m1 - n1);
            lacc[0] *= a0; lacc[1] *= a0; lacc[2] *= a1; lacc[3] *= a1;
#pragma unroll
            for (int j = 0; j < 8; j++) {
                o[j][0] *= a0; o[j][1] *= a0; o[j][2] *= a1; o[j][3] *= a1;
            }
            m0 = n0; m1 = n1;
        }

        // ---- P = exp2(s - m) in fp16x2, as MMA A-fragments ----
        uint32_t pf[4][4];
#pragma unroll
        for (int f = 0; f < 4; f++) {
            int j0 = 2 * f, j1 = 2 * f + 1;
            pf[f][0] = ex2_h2(s[j0][0] - m0, s[j0][1] - m0);
            pf[f][1] = ex2_h2(s[j0][2] - m1, s[j0][3] - m1);
            pf[f][2] = ex2_h2(s[j1][0] - m0, s[j1][1] - m0);
            pf[f][3] = ex2_h2(s[j1][2] - m1, s[j1][3] - m1);
        }

        // ---- l += P · 1 ----
        mma_hf(lacc, pf[0], ONES2, ONES2);
        mma_hf(lacc, pf[1], ONES2, ONES2);
        mma_hf(lacc, pf[2], ONES2, ONES2);
        mma_hf(lacc, pf[3], ONES2, ONES2);

        // ---- O += P V : fp16 single-pass ----
#pragma unroll
        for (int kcp = 0; kcp < 2; kcp++) {
#pragma unroll
            for (int j2 = 0; j2 < 8; j2++) {
                uint32_t va = vhb + (32 * kcp + lane) * FPITCH + j2 * 16;
                uint32_t v0, v1, v2, v3;
                ldsm4t(v0, v1, v2, v3, va);
                mma_hf(o[j2], pf[2 * kcp],     v0, v1);
                mma_hf(o[j2], pf[2 * kcp + 1], v2, v3);
            }
        }
    }

    // ---- epilogue ----
    float inv0 = 1.f / lacc[0], inv1 = 1.f / lacc[2];
    size_t r0 = batch_row + (size_t)qt * 128 + w * 16 + grp;
#pragma unroll
    for (int j2 = 0; j2 < 8; j2++) {
        int c = h * HDIM + 8 * j2 + 2 * qr;
        *(uint32_t*)&Out[r0 * EMB + c]       = packh(o[j2][0] * inv0, o[j2][1] * inv0);
        *(uint32_t*)&Out[(r0 + 8) * EMB + c] = packh(o[j2][2] * inv1, o[j2][3] * inv1);
    }
}

// ------------------------------------------------------------------
extern "C" void kernel_launch(void* const* d_in, const int* in_sizes, int n_in,
                              void* d_out, int out_size) {
    const float* x  = (const float*)d_in[0];
    const float* Wq = (const float*)d_in[1];
    const float* Wk = (const float*)d_in[2];
    const float* Wv = (const float*)d_in[3];
    const float* Wo = (const float*)d_in[4];
    float* out = (float*)d_out;

    __nv_bfloat16 *gxh, *gxl, *gBqh, *gBql, *gQh, *gQl;
    __half *gxf, *gBvf, *gBof, *gAt;
    cudaGetSymbolAddress((void**)&gxh,  g_xh);
    cudaGetSymbolAddress((void**)&gxl,  g_xl);
    cudaGetSymbolAddress((void**)&gxf,  g_xf);
    cudaGetSymbolAddress((void**)&gBqh, g_Bqh);
    cudaGetSymbolAddress((void**)&gBql, g_Bql);
    cudaGetSymbolAddress((void**)&gBvf, g_Bvf);
    cudaGetSymbolAddress((void**)&gBof, g_Bof);
    cudaGetSymbolAddress((void**)&gQh,  g_QKVh);
    cudaGetSymbolAddress((void**)&gQl,  g_QKVl);
    cudaGetSymbolAddress((void**)&gAt,  g_At);

    const int GPSMEM = 3 * GSTAGE;     // 98304
    const int GOSMEM = 4 * GOSTAGE;    // 65536
    const int FSMEM  = 4 * FSTAGE;     // 110592
    cudaFuncSetAttribute(gemm_proj, cudaFuncAttributeMaxDynamicSharedMemorySize, GPSMEM);
    cudaFuncSetAttribute(gemm_o,    cudaFuncAttributeMaxDynamicSharedMemorySize, GOSMEM);
    cudaFuncSetAttribute(flash_mma, cudaFuncAttributeMaxDynamicSharedMemorySize, FSMEM);

    split_x<<<(MROWS * EMB + 255) / 256, 256>>>(x, gxh, gxl, gxf, MROWS * EMB);
    pack_qkv_t<<<dim3(16, 16, 3), 256>>>(Wq, Wk, Wv, gBqh, gBql, gBvf);
    pack_wo<<<(EMB * EMB + 255) / 256, 256>>>(Wo, gBof);

    gemm_proj<<<dim3(24, MROWS / 128), 256, GPSMEM>>>(
        gxh, gxl, gBqh, gBql, gQh, gQl,
        gxf, gBvf, reinterpret_cast<__half*>(gQh) + 2 * EMB);

    flash_mma<<<dim3(SEQ / 128, HEADS, BATCH), 256, FSMEM>>>(gQh, gQl, gAt);

    gemm_o<<<dim3(EMB / 128, MROWS / 128), 256, GOSMEM>>>(gAt, gBof, out, EMB);
}

// round 15
// speedup vs baseline: 1.5322x; 1.5322x over previous
#include <cuda_runtime.h>
#include <cuda_bf16.h>
#include <cuda_fp16.h>
#include <stdint.h>
#include <math.h>

#define BATCH 2
#define SEQ   2048
#define EMB   1024
#define HEADS 16
#define HDIM  64
#define MROWS (BATCH*SEQ)   /* 4096 */
#define QKVN  (3*EMB)       /* 3072 */
#define KDIM  EMB

#define QSCALE  0.02209708691207961f
#define QSCALE2 (QSCALE * 1.4426950408889634f)
#define SKIP_T  25.0f

// ---------------- scratch ----------------
__device__ __align__(256) __nv_bfloat16 g_xh [(size_t)MROWS*EMB];
__device__ __align__(256) __nv_bfloat16 g_xl [(size_t)MROWS*EMB];
__device__ __align__(256) __half        g_xf [(size_t)MROWS*EMB];
__device__ __align__(256) __nv_bfloat16 g_Bqh[(size_t)2*EMB*EMB];
__device__ __align__(256) __nv_bfloat16 g_Bql[(size_t)2*EMB*EMB];
__device__ __align__(256) __half        g_Bvf[(size_t)EMB*EMB];
__device__ __align__(256) __half        g_Bof[(size_t)EMB*EMB];
__device__ __align__(256) __nv_bfloat16 g_QKVh[(size_t)MROWS*QKVN];  /* V region = fp16 bits */
__device__ __align__(256) __nv_bfloat16 g_QKVl[(size_t)MROWS*QKVN];
__device__ __align__(256) __half        g_At [(size_t)MROWS*EMB];

// ---------------- helpers ----------------
__device__ __forceinline__ uint32_t cvta_smem(const void* p) {
    uint32_t a;
    asm("{ .reg .u64 t; cvta.to.shared.u64 t, %1; cvt.u32.u64 %0, t; }" : "=r"(a) : "l"(p));
    return a;
}
__device__ __forceinline__ void cp16(uint32_t dst, const void* src) {
    asm volatile("cp.async.cg.shared.global [%0], [%1], 16;" :: "r"(dst), "l"(src));
}
#define CP_COMMIT() asm volatile("cp.async.commit_group;" ::: "memory")
#define CP_WAIT2()  asm volatile("cp.async.wait_group 2;" ::: "memory")
#define CP_WAIT1()  asm volatile("cp.async.wait_group 1;" ::: "memory")
#define CP_WAIT0()  asm volatile("cp.async.wait_group 0;" ::: "memory")

__device__ __forceinline__ void ldsm4(uint32_t& r0, uint32_t& r1, uint32_t& r2, uint32_t& r3,
                                      uint32_t addr) {
    asm volatile("ldmatrix.sync.aligned.m8n8.x4.shared.b16 {%0,%1,%2,%3},[%4];"
                 : "=r"(r0), "=r"(r1), "=r"(r2), "=r"(r3) : "r"(addr));
}
__device__ __forceinline__ void ldsm4t(uint32_t& r0, uint32_t& r1, uint32_t& r2, uint32_t& r3,
                                       uint32_t addr) {
    asm volatile("ldmatrix.sync.aligned.m8n8.x4.trans.shared.b16 {%0,%1,%2,%3},[%4];"
                 : "=r"(r0), "=r"(r1), "=r"(r2), "=r"(r3) : "r"(addr));
}
__device__ __forceinline__ void mma_bf(float c[4], const uint32_t a[4], uint32_t b0, uint32_t b1) {
    asm("mma.sync.aligned.m16n8k16.row.col.f32.bf16.bf16.f32 "
        "{%0,%1,%2,%3}, {%4,%5,%6,%7}, {%8,%9}, {%0,%1,%2,%3};"
        : "+f"(c[0]), "+f"(c[1]), "+f"(c[2]), "+f"(c[3])
        : "r"(a[0]), "r"(a[1]), "r"(a[2]), "r"(a[3]), "r"(b0), "r"(b1));
}
__device__ __forceinline__ void mma_hf(float c[4], const uint32_t a[4], uint32_t b0, uint32_t b1) {
    asm("mma.sync.aligned.m16n8k16.row.col.f32.f16.f16.f32 "
        "{%0,%1,%2,%3}, {%4,%5,%6,%7}, {%8,%9}, {%0,%1,%2,%3};"
        : "+f"(c[0]), "+f"(c[1]), "+f"(c[2]), "+f"(c[3])
        : "r"(a[0]), "r"(a[1]), "r"(a[2]), "r"(a[3]), "r"(b0), "r"(b1));
}
__device__ __forceinline__ float ex2(float x) {
    float r;
    asm("ex2.approx.ftz.f32 %0, %1;" : "=f"(r) : "f"(x));
    return r;
}
__device__ __forceinline__ uint32_t ex2_h2(float x, float y) {
    uint32_t h, r;
    asm("cvt.rn.f16x2.f32 %0, %1, %2;" : "=r"(h) : "f"(y), "f"(x));
    asm("ex2.approx.f16x2 %0, %1;" : "=r"(r) : "r"(h));
    return r;
}
__device__ __forceinline__ uint32_t packbf(float x, float y) {
    __nv_bfloat162 t = __floats2bfloat162_rn(x, y);
    return *reinterpret_cast<uint32_t*>(&t);
}
__device__ __forceinline__ uint32_t packres(float x, float y, uint32_t h) {
    __nv_bfloat162 hh = *reinterpret_cast<__nv_bfloat162*>(&h);
    return packbf(x - __bfloat162float(hh.x), y - __bfloat162float(hh.y));
}
__device__ __forceinline__ uint32_t packh(float x, float y) {
    __half2 t = __floats2half2_rn(x, y);
    return *reinterpret_cast<uint32_t*>(&t);
}
__device__ __forceinline__ void split2(float v, __nv_bfloat16& hi, __nv_bfloat16& lo) {
    hi = __float2bfloat16(v);
    lo = __float2bfloat16(v - __bfloat162float(hi));
}

// ---------------- packing kernels ----------------
__global__ void split_x(const float* __restrict__ x, __nv_bfloat16* __restrict__ hi,
                        __nv_bfloat16* __restrict__ lo, __half* __restrict__ hf, int n) {
    int i = blockIdx.x * blockDim.x + threadIdx.x;
    if (i >= n) return;
    float v = x[i];
    split2(v, hi[i], lo[i]);
    hf[i] = __float2half(v);
}

__global__ void pack_qkv_t(const float* __restrict__ Wq, const float* __restrict__ Wk,
                           const float* __restrict__ Wv,
                           __nv_bfloat16* __restrict__ hi, __nv_bfloat16* __restrict__ lo,
                           __half* __restrict__ vf) {
    __shared__ float ts[64][65];
    const int tid = threadIdx.x;
    const int kb = blockIdx.x, hid = blockIdx.y, wh = blockIdx.z;
    const float* src = (wh == 0) ? Wq : (wh == 1) ? Wk : Wv;
    const float sc = (wh == 0) ? QSCALE2 : 1.0f;

#pragma unroll
    for (int p = 0; p < 16; p++) {
        int kr = (tid >> 6) + p * 4;
        int i  = tid & 63;
        ts[kr][i] = src[(size_t)hid * (EMB * HDIM) + (size_t)(kb * 64 + kr) * HDIM + i];
    }
    __syncthreads();
#pragma unroll
    for (int p = 0; p < 16; p++) {
        int i = (tid >> 6) + p * 4;
        int k = tid & 63;
        float v = ts[k][i] * sc;
        if (wh == 2) {
            size_t o = ((size_t)(hid * 64 + i) << 10) + kb * 64 + k;
            vf[o] = __float2half(v);
        } else {
            size_t o = ((size_t)(wh * 1024 + hid * 64 + i) << 10) + kb * 64 + k;
            split2(v, hi[o], lo[o]);
        }
    }
}

__global__ void pack_wo(const float* __restrict__ Wo, __half* __restrict__ hf) {
    int idx = blockIdx.x * blockDim.x + threadIdx.x;
    if (idx >= EMB * EMB) return;
    hf[idx] = __float2half(Wo[idx]);
}

// ---------------- merged projection: QK (bf16 3-pass) + V (fp16 1-pass) ----------------
#define GTILE  8192
#define GSTAGE 32768
#define GVSTAGE 16384
#define GNC    (KDIM/32)

__global__ __launch_bounds__(256, 2)
void gemm_proj(const __nv_bfloat16* __restrict__ Ah, const __nv_bfloat16* __restrict__ Al,
               const __nv_bfloat16* __restrict__ Bh, const __nv_bfloat16* __restrict__ Bl,
               __nv_bfloat16* __restrict__ Ch, __nv_bfloat16* __restrict__ Cl,
               const __half* __restrict__ Af, const __half* __restrict__ Bvf,
               __half* __restrict__ Cv) {
    extern __shared__ __align__(16) char smraw[];
    uint32_t smb = cvta_smem(smraw);
    const int tid = threadIdx.x, lane = tid & 31, wid = tid >> 5;
    const int wm = wid & 3, wn = wid >> 2;
    const int mb = blockIdx.y;
    const int grp = lane >> 2, qr = lane & 3;

    float acc[2][8][4];
#pragma unroll
    for (int a = 0; a < 2; a++)
#pragma unroll
        for (int b = 0; b < 8; b++)
#pragma unroll
            for (int c = 0; c < 4; c++) acc[a][b][c] = 0.f;

    if (blockIdx.x < 16) {
        // ---------- QK path: bf16 3-pass, 3-stage ----------
        const int nb = blockIdx.x;
        const __nv_bfloat16* gsrc[4] = {
            Ah + (size_t)mb * 128 * KDIM, Al + (size_t)mb * 128 * KDIM,
            Bh + (size_t)nb * 128 * KDIM, Bl + (size_t)nb * 128 * KDIM };

        auto ldchunk = [&](int buf, int ck) {
            uint32_t bb = smb + buf * GSTAGE;
#pragma unroll
            for (int q = 0; q < 8; q++) {
                int i = q * 256 + tid;
                int t = i >> 9;
                int r = (i >> 2) & 127;
                int c16 = i & 3;
                uint32_t dst = bb + t * GTILE + r * 64 + ((c16 ^ ((r >> 1) & 3)) << 4);
                cp16(dst, gsrc[t] + (size_t)r * KDIM + ck * 32 + c16 * 8);
            }
        };

        ldchunk(0, 0); CP_COMMIT();
        ldchunk(1, 1); CP_COMMIT();

        int buf = 0, rb = 2;
        for (int c = 0; c < GNC; c++) {
            if (c + 1 < GNC) CP_WAIT1(); else CP_WAIT0();
            __syncthreads();
            if (c + 2 < GNC) {
                ldchunk(rb, c + 2); CP_COMMIT();
                rb = (rb == 2) ? 0 : rb + 1;
            }
            uint32_t bb = smb + buf * GSTAGE;

#pragma unroll
            for (int s = 0; s < 2; s++) {
                uint32_t ah[2][4], al[2][4];
#pragma unroll
                for (int mt = 0; mt < 2; mt++) {
                    uint32_t row = 32 * wm + 16 * mt + ((lane >> 3) & 1) * 8 + (lane & 7);
                    uint32_t kb  = (lane >> 4) * 16 + s * 32;
                    uint32_t ad  = bb + row * 64 + ((((kb >> 4)) ^ ((row >> 1) & 3)) << 4);
                    ldsm4(ah[mt][0], ah[mt][1], ah[mt][2], ah[mt][3], ad);
                    ldsm4(al[mt][0], al[mt][1], al[mt][2], al[mt][3], ad + GTILE);
                }
#pragma unroll
                for (int np = 0; np < 4; np++) {
                    uint32_t row = 64 * wn + 16 * np + ((lane >> 4) & 1) * 8 + (lane & 7);
                    uint32_t kb  = ((lane >> 3) & 1) * 16 + s * 32;
                    uint32_t bd  = bb + 2 * GTILE + row * 64 + ((((kb >> 4)) ^ ((row >> 1) & 3)) << 4);
                    uint32_t bh0, bh1, bh2, bh3, bl0, bl1, bl2, bl3;
                    ldsm4(bh0, bh1, bh2, bh3, bd);
                    ldsm4(bl0, bl1, bl2, bl3, bd + GTILE);
#pragma unroll
                    for (int p = 0; p < 3; p++) {
                        const uint32_t* a0 = (p == 1) ? al[0] : ah[0];
                        const uint32_t* a1 = (p == 1) ? al[1] : ah[1];
                        uint32_t c0 = (p == 2) ? bl0 : bh0, c1 = (p == 2) ? bl1 : bh1;
                        uint32_t c2 = (p == 2) ? bl2 : bh2, c3 = (p == 2) ? bl3 : bh3;
                        mma_bf(acc[0][2 * np],     a0, c0, c1);
                        mma_bf(acc[1][2 * np],     a1, c0, c1);
                        mma_bf(acc[0][2 * np + 1], a0, c2, c3);
                        mma_bf(acc[1][2 * np + 1], a1, c2, c3);
                    }
                }
            }
            buf = (buf == 2) ? 0 : buf + 1;
        }

#pragma unroll
        for (int mt = 0; mt < 2; mt++) {
            size_t r0 = (size_t)mb * 128 + 32 * wm + 16 * mt + grp;
#pragma unroll
            for (int nt = 0; nt < 8; nt++) {
                int col = nb * 128 + 64 * wn + 8 * nt + 2 * qr;
                float* c4 = acc[mt][nt];
                uint32_t h0 = packbf(c4[0], c4[1]), l0 = packres(c4[0], c4[1], h0);
                uint32_t h1 = packbf(c4[2], c4[3]), l1 = packres(c4[2], c4[3], h1);
                *(uint32_t*)&Ch[r0 * QKVN + col]       = h0;
                *(uint32_t*)&Cl[r0 * QKVN + col]       = l0;
                *(uint32_t*)&Ch[(r0 + 8) * QKVN + col] = h1;
                *(uint32_t*)&Cl[(r0 + 8) * QKVN + col] = l1;
            }
        }
    } else {
        // ---------- V path: fp16 1-pass, 4-stage ----------
        const int nb = blockIdx.x - 16;
        const __half* gsrc[2] = { Af + (size_t)mb * 128 * KDIM, Bvf + (size_t)nb * 128 * KDIM };

        auto ldchunk = [&](int buf, int ck) {
            uint32_t bb = smb + buf * GVSTAGE;
#pragma unroll
            for (int q = 0; q < 4; q++) {
                int i = q * 256 + tid;
                int t = i >> 9;
                int r = (i >> 2) & 127;
                int c16 = i & 3;
                uint32_t dst = bb + t * GTILE + r * 64 + ((c16 ^ ((r >> 1) & 3)) << 4);
                cp16(dst, gsrc[t] + (size_t)r * KDIM + ck * 32 + c16 * 8);
            }
        };

        ldchunk(0, 0); CP_COMMIT();
        ldchunk(1, 1); CP_COMMIT();
        ldchunk(2, 2); CP_COMMIT();

        int rb = 3;
        for (int c = 0; c < GNC; c++) {
            int rem = GNC - c;
            if (rem >= 3) CP_WAIT2(); else if (rem == 2) CP_WAIT1(); else CP_WAIT0();
            __syncthreads();
            if (c + 3 < GNC) {
                ldchunk(rb, c + 3); CP_COMMIT();
                rb = (rb + 1) & 3;
            }
            uint32_t bb = smb + (c & 3) * GVSTAGE;

#pragma unroll
            for (int s = 0; s < 2; s++) {
                uint32_t ah[2][4];
#pragma unroll
                for (int mt = 0; mt < 2; mt++) {
                    uint32_t row = 32 * wm + 16 * mt + ((lane >> 3) & 1) * 8 + (lane & 7);
                    uint32_t kb  = (lane >> 4) * 16 + s * 32;
                    uint32_t ad  = bb + row * 64 + ((((kb >> 4)) ^ ((row >> 1) & 3)) << 4);
                    ldsm4(ah[mt][0], ah[mt][1], ah[mt][2], ah[mt][3], ad);
                }
#pragma unroll
                for (int np = 0; np < 4; np++) {
                    uint32_t row = 64 * wn + 16 * np + ((lane >> 4) & 1) * 8 + (lane & 7);
                    uint32_t kb  = ((lane >> 3) & 1) * 16 + s * 32;
                    uint32_t bd  = bb + GTILE + row * 64 + ((((kb >> 4)) ^ ((row >> 1) & 3)) << 4);
                    uint32_t b0, b1, b2, b3;
                    ldsm4(b0, b1, b2, b3, bd);
                    mma_hf(acc[0][2 * np],     ah[0], b0, b1);
                    mma_hf(acc[1][2 * np],     ah[1], b0, b1);
                    mma_hf(acc[0][2 * np + 1], ah[0], b2, b3);
                    mma_hf(acc[1][2 * np + 1], ah[1], b2, b3);
                }
            }
        }

#pragma unroll
        for (int mt = 0; mt < 2; mt++) {
            size_t r0 = (size_t)mb * 128 + 32 * wm + 16 * mt + grp;
#pragma unroll
            for (int nt = 0; nt < 8; nt++) {
                int col = nb * 128 + 64 * wn + 8 * nt + 2 * qr;
                float* c4 = acc[mt][nt];
                *(uint32_t*)&Cv[r0 * QKVN + col]       = packh(c4[0], c4[1]);
                *(uint32_t*)&Cv[(r0 + 8) * QKVN + col] = packh(c4[2], c4[3]);
            }
        }
    }
}

// ---------------- GEMM-O: fp16 1-pass, 4-stage ----------------
#define GOSTAGE 16384

__global__ __launch_bounds__(256, 2)
void gemm_o(const __half* __restrict__ A, const __half* __restrict__ B,
            float* __restrict__ C, int N) {
    extern __shared__ __align__(16) char smraw[];
    uint32_t smb = cvta_smem(smraw);
    const int tid = threadIdx.x, lane = tid & 31, wid = tid >> 5;
    const int wm = wid & 3, wn = wid >> 2;
    const int nb = blockIdx.x, mb = blockIdx.y;

    const __half* gsrc[2] = { A + (size_t)mb * 128 * KDIM, B + (size_t)nb * 128 * KDIM };

    auto ldchunk = [&](int buf, int ck) {
        uint32_t bb = smb + buf * GOSTAGE;
#pragma unroll
        for (int q = 0; q < 4; q++) {
            int i = q * 256 + tid;
            int t = i >> 9;
            int r = (i >> 2) & 127;
            int c16 = i & 3;
            uint32_t dst = bb + t * GTILE + r * 64 + ((c16 ^ ((r >> 1) & 3)) << 4);
            cp16(dst, gsrc[t] + (size_t)r * KDIM + ck * 32 + c16 * 8);
        }
    };

    ldchunk(0, 0); CP_COMMIT();
    ldchunk(1, 1); CP_COMMIT();
    ldchunk(2, 2); CP_COMMIT();

    float acc[2][8][4];
#pragma unroll
    for (int a = 0; a < 2; a++)
#pragma unroll
        for (int b = 0; b < 8; b++)
#pragma unroll
            for (int c = 0; c < 4; c++) acc[a][b][c] = 0.f;

    int rb = 3;
    for (int c = 0; c < GNC; c++) {
        int rem = GNC - c;
        if (rem >= 3) CP_WAIT2(); else if (rem == 2) CP_WAIT1(); else CP_WAIT0();
        __syncthreads();
        if (c + 3 < GNC) {
            ldchunk(rb, c + 3); CP_COMMIT();
            rb = (rb + 1) & 3;
        }
        uint32_t bb = smb + (c & 3) * GOSTAGE;

#pragma unroll
        for (int s = 0; s < 2; s++) {
            uint32_t ah[2][4];
#pragma unroll
            for (int mt = 0; mt < 2; mt++) {
                uint32_t row = 32 * wm + 16 * mt + ((lane >> 3) & 1) * 8 + (lane & 7);
                uint32_t kb  = (lane >> 4) * 16 + s * 32;
                uint32_t ad  = bb + row * 64 + ((((kb >> 4)) ^ ((row >> 1) & 3)) << 4);
                ldsm4(ah[mt][0], ah[mt][1], ah[mt][2], ah[mt][3], ad);
            }
#pragma unroll
            for (int np = 0; np < 4; np++) {
                uint32_t row = 64 * wn + 16 * np + ((lane >> 4) & 1) * 8 + (lane & 7);
                uint32_t kb  = ((lane >> 3) & 1) * 16 + s * 32;
                uint32_t bd  = bb + GTILE + row * 64 + ((((kb >> 4)) ^ ((row >> 1) & 3)) << 4);
                uint32_t b0, b1, b2, b3;
                ldsm4(b0, b1, b2, b3, bd);
                mma_hf(acc[0][2 * np],     ah[0], b0, b1);
                mma_hf(acc[1][2 * np],     ah[1], b0, b1);
                mma_hf(acc[0][2 * np + 1], ah[0], b2, b3);
                mma_hf(acc[1][2 * np + 1], ah[1], b2, b3);
            }
        }
    }

    const int grp = lane >> 2, qr = lane & 3;
#pragma unroll
    for (int mt = 0; mt < 2; mt++) {
        size_t r0 = (size_t)mb * 128 + 32 * wm + 16 * mt + grp;
#pragma unroll
        for (int nt = 0; nt < 8; nt++) {
            int col = nb * 128 + 64 * wn + 8 * nt + 2 * qr;
            float* c4 = acc[mt][nt];
            *(float2*)&C[r0 * N + col]       = make_float2(c4[0], c4[1]);
            *(float2*)&C[(r0 + 8) * N + col] = make_float2(c4[2], c4[3]);
        }
    }
}

// ---------------- Flash attention: fp16x2 softmax + MMA l-sum ----------------
#define FPITCH 144
#define FTILE  9216
#define FSTAGE 27648
#define NKT    (SEQ/64)
#define ONES2  0x3C003C00u

__global__ __launch_bounds__(256, 2)
void flash_mma(const __nv_bfloat16* __restrict__ Qh, const __nv_bfloat16* __restrict__ Ql,
               __half* __restrict__ Out) {
    extern __shared__ __align__(16) char smraw[];
    uint32_t smb = cvta_smem(smraw);

    const int tid = threadIdx.x, lane = tid & 31, w = tid >> 5;
    const int grp = lane >> 2, qr = lane & 3;
    const int qt = blockIdx.x, h = blockIdx.y, b = blockIdx.z;

    const size_t batch_row = (size_t)b * SEQ;

    const __nv_bfloat16* kvsrc[3] = {
        Qh + batch_row * QKVN + EMB + h * HDIM,
        Ql + batch_row * QKVN + EMB + h * HDIM,
        Qh + batch_row * QKVN + 2 * EMB + h * HDIM };

    auto ldtile = [&](int bf, int kt) {
        uint32_t bb = smb + bf * FSTAGE;
        size_t rbase = (size_t)kt * 64;
#pragma unroll
        for (int q = 0; q < 6; q++) {
            int i = q * 256 + tid;
            int t = i >> 9;
            int r = (i >> 3) & 63;
            int sg = i & 7;
            cp16(bb + t * FTILE + r * FPITCH + sg * 16,
                 kvsrc[t] + (rbase + r) * QKVN + sg * 8);
        }
    };

    uint32_t qh[4][4], ql[4][4];
    {
        size_t r0 = batch_row + (size_t)qt * 128 + w * 16 + grp;
        const __nv_bfloat16* qb_h = Qh + r0 * QKVN + h * HDIM;
        const __nv_bfloat16* qb_l = Ql + r0 * QKVN + h * HDIM;
#pragma unroll
        for (int t = 0; t < 4; t++) {
            int c0 = t * 16 + 2 * qr;
            qh[t][0] = *(const uint32_t*)(qb_h + c0);
            qh[t][1] = *(const uint32_t*)(qb_h + 8 * QKVN + c0);
            qh[t][2] = *(const uint32_t*)(qb_h + c0 + 8);
            qh[t][3] = *(const uint32_t*)(qb_h + 8 * QKVN + c0 + 8);
            ql[t][0] = *(const uint32_t*)(qb_l + c0);
            ql[t][1] = *(const uint32_t*)(qb_l + 8 * QKVN + c0);
            ql[t][2] = *(const uint32_t*)(qb_l + c0 + 8);
            ql[t][3] = *(const uint32_t*)(qb_l + 8 * QKVN + c0 + 8);
        }
    }

    float o[8][4];
#pragma unroll
    for (int j = 0; j < 8; j++)
#pragma unroll
        for (int c = 0; c < 4; c++) o[j][c] = 0.f;
    float lacc[4] = {0.f, 0.f, 0.f, 0.f};
    float m0 = -1e30f, m1 = -1e30f;

    ldtile(0, 0); CP_COMMIT();
    ldtile(1, 1); CP_COMMIT();
    ldtile(2, 2); CP_COMMIT();

    int rb = 3;
    for (int kt = 0; kt < NKT; kt++) {
        int rem = NKT - kt;
        if (rem >= 3) CP_WAIT2(); else if (rem == 2) CP_WAIT1(); else CP_WAIT0();
        __syncthreads();
        if (kt + 3 < NKT) {
            ldtile(rb, kt + 3); CP_COMMIT();
            rb = (rb + 1) & 3;
        }
        uint32_t sb  = smb + (kt & 3) * FSTAGE;
        uint32_t khb = sb, vhb = sb + 2 * FTILE;

        // ---- S = Q K^T (16 x 64 per warp), bf16 3-pass ----
        float s[8][4];
#pragma unroll
        for (int j = 0; j < 8; j++) {
            uint32_t ka = khb + (8 * j + (lane & 7)) * FPITCH + (lane >> 3) * 16;
            uint32_t la = ka + FTILE;
            uint32_t h0, h1, h2, h3, h4, h5, h6, h7;
            uint32_t e0, e1, e2, e3, e4, e5, e6, e7;
            ldsm4(h0, h1, h2, h3, ka);
            ldsm4(h4, h5, h6, h7, ka + 64);
            ldsm4(e0, e1, e2, e3, la);
            ldsm4(e4, e5, e6, e7, la + 64);
            s[j][0] = s[j][1] = s[j][2] = s[j][3] = 0.f;
            mma_bf(s[j], qh[0], h0, h1); mma_bf(s[j], ql[0], h0, h1); mma_bf(s[j], qh[0], e0, e1);
            mma_bf(s[j], qh[1], h2, h3); mma_bf(s[j], ql[1], h2, h3); mma_bf(s[j], qh[1], e2, e3);
            mma_bf(s[j], qh[2], h4, h5); mma_bf(s[j], ql[2], h4, h5); mma_bf(s[j], qh[2], e4, e5);
            mma_bf(s[j], qh[3], h6, h7); mma_bf(s[j], ql[3], h6, h7); mma_bf(s[j], qh[3], e6, e7);
        }

        // ---- maxima (quad-reduced) ----
        float t0 = -1e30f, t1 = -1e30f;
#pragma unroll
        for (int j = 0; j < 8; j++) {
            t0 = fmaxf(t0, fmaxf(s[j][0], s[j][1]));
            t1 = fmaxf(t1, fmaxf(s[j][2], s[j][3]));
        }
        t0 = fmaxf(t0, __shfl_xor_sync(0xffffffffu, t0, 1));
        t0 = fmaxf(t0, __shfl_xor_sync(0xffffffffu, t0, 2));
        t1 = fmaxf(t1, __shfl_xor_sync(0xffffffffu, t1, 1));
        t1 = fmaxf(t1, __shfl_xor_sync(0xffffffffu, t1, 2));

        bool negl = (t0 < m0 - SKIP_T) && (t1 < m1 - SKIP_T);
        if (__all_sync(0xffffffffu, negl)) continue;

        bool newmax = (t0 > m0) || (t1 > m1);
        if (newmax) {
            float n0 = fmaxf(m0, t0), n1 = fmaxf(m1, t1);
            float a0 = ex2(m0 - n0), a1 = ex2(m1 - n1);
            lacc[0] *= a0; lacc[1] *= a0; lacc[2] *= a1; lacc[3] *= a1;
#pragma unroll
            for (int j = 0; j < 8; j++) {
                o[j][0] *= a0; o[j][1] *= a0; o[j][2] *= a1; o[j][3] *= a1;
            }
            m0 = n0; m1 = n1;
        }

        // ---- P = exp2(s - m) in fp16x2, as MMA A-fragments ----
        uint32_t pf[4][4];
#pragma unroll
        for (int f = 0; f < 4; f++) {
            int j0 = 2 * f, j1 = 2 * f + 1;
            pf[f][0] = ex2_h2(s[j0][0] - m0, s[j0][1] - m0);
            pf[f][1] = ex2_h2(s[j0][2] - m1, s[j0][3] - m1);
            pf[f][2] = ex2_h2(s[j1][0] - m0, s[j1][1] - m0);
            pf[f][3] = ex2_h2(s[j1][2] - m1, s[j1][3] - m1);
        }

        // ---- l += P · 1 ----
        mma_hf(lacc, pf[0], ONES2, ONES2);
        mma_hf(lacc, pf[1], ONES2, ONES2);
        mma_hf(lacc, pf[2], ONES2, ONES2);
        mma_hf(lacc, pf[3], ONES2, ONES2);

        // ---- O += P V : fp16 single-pass ----
#pragma unroll
        for (int kcp = 0; kcp < 2; kcp++) {
#pragma unroll
            for (int j2 = 0; j2 < 8; j2++) {
                uint32_t va = vhb + (32 * kcp + lane) * FPITCH + j2 * 16;
                uint32_t v0, v1, v2, v3;
                ldsm4t(v0, v1, v2, v3, va);
                mma_hf(o[j2], pf[2 * kcp],     v0, v1);
                mma_hf(o[j2], pf[2 * kcp + 1], v2, v3);
            }
        }
    }

    // ---- epilogue ----
    float inv0 = 1.f / lacc[0], inv1 = 1.f / lacc[2];
    size_t r0 = batch_row + (size_t)qt * 128 + w * 16 + grp;
#pragma unroll
    for (int j2 = 0; j2 < 8; j2++) {
        int c = h * HDIM + 8 * j2 + 2 * qr;
        *(uint32_t*)&Out[r0 * EMB + c]       = packh(o[j2][0] * inv0, o[j2][1] * inv0);
        *(uint32_t*)&Out[(r0 + 8) * EMB + c] = packh(o[j2][2] * inv1, o[j2][3] * inv1);
    }
}

// ------------------------------------------------------------------
extern "C" void kernel_launch(void* const* d_in, const int* in_sizes, int n_in,
                              void* d_out, int out_size) {
    const float* x  = (const float*)d_in[0];
    const float* Wq = (const float*)d_in[1];
    const float* Wk = (const float*)d_in[2];
    const float* Wv = (const float*)d_in[3];
    const float* Wo = (const float*)d_in[4];
    float* out = (float*)d_out;

    __nv_bfloat16 *gxh, *gxl, *gBqh, *gBql, *gQh, *gQl;
    __half *gxf, *gBvf, *gBof, *gAt;
    cudaGetSymbolAddress((void**)&gxh,  g_xh);
    cudaGetSymbolAddress((void**)&gxl,  g_xl);
    cudaGetSymbolAddress((void**)&gxf,  g_xf);
    cudaGetSymbolAddress((void**)&gBqh, g_Bqh);
    cudaGetSymbolAddress((void**)&gBql, g_Bql);
    cudaGetSymbolAddress((void**)&gBvf, g_Bvf);
    cudaGetSymbolAddress((void**)&gBof, g_Bof);
    cudaGetSymbolAddress((void**)&gQh,  g_QKVh);
    cudaGetSymbolAddress((void**)&gQl,  g_QKVl);
    cudaGetSymbolAddress((void**)&gAt,  g_At);

    const int GPSMEM = 3 * GSTAGE;     // 98304
    const int GOSMEM = 4 * GOSTAGE;    // 65536
    const int FSMEM  = 4 * FSTAGE;     // 110592
    cudaFuncSetAttribute(gemm_proj, cudaFuncAttributeMaxDynamicSharedMemorySize, GPSMEM);
    cudaFuncSetAttribute(gemm_o,    cudaFuncAttributeMaxDynamicSharedMemorySize, GOSMEM);
    cudaFuncSetAttribute(flash_mma, cudaFuncAttributeMaxDynamicSharedMemorySize, FSMEM);

    split_x<<<(MROWS * EMB + 255) / 256, 256>>>(x, gxh, gxl, gxf, MROWS * EMB);
    pack_qkv_t<<<dim3(16, 16, 3), 256>>>(Wq, Wk, Wv, gBqh, gBql, gBvf);
    pack_wo<<<(EMB * EMB + 255) / 256, 256>>>(Wo, gBof);

    gemm_proj<<<dim3(24, MROWS / 128), 256, GPSMEM>>>(
        gxh, gxl, gBqh, gBql, gQh, gQl,
        gxf, gBvf, reinterpret_cast<__half*>(gQh) + 2 * EMB);

    flash_mma<<<dim3(SEQ / 128, HEADS, BATCH), 256, FSMEM>>>(gQh, gQl, gAt);

    gemm_o<<<dim3(EMB / 128, MROWS / 128), 256, GOSMEM>>>(gAt, gBof, out, EMB);
}

// round 16
// speedup vs baseline: 1.5517x; 1.0127x over previous
#include <cuda_runtime.h>
#include <cuda_bf16.h>
#include <cuda_fp16.h>
#include <stdint.h>
#include <math.h>

#define BATCH 2
#define SEQ   2048
#define EMB   1024
#define HEADS 16
#define HDIM  64
#define MROWS (BATCH*SEQ)   /* 4096 */
#define QKVN  (3*EMB)       /* 3072 */
#define KDIM  EMB

#define QSCALE  0.02209708691207961f
#define QSCALE2 (QSCALE * 1.4426950408889634f)
#define SKIP_T  25.0f

// ---------------- scratch ----------------
__device__ __align__(256) __nv_bfloat16 g_xh [(size_t)MROWS*EMB];
__device__ __align__(256) __nv_bfloat16 g_xl [(size_t)MROWS*EMB];
__device__ __align__(256) __half        g_xf [(size_t)MROWS*EMB];
__device__ __align__(256) __nv_bfloat16 g_Bqh[(size_t)2*EMB*EMB];
__device__ __align__(256) __nv_bfloat16 g_Bql[(size_t)2*EMB*EMB];
__device__ __align__(256) __half        g_Bvf[(size_t)EMB*EMB];
__device__ __align__(256) __half        g_Bof[(size_t)EMB*EMB];
__device__ __align__(256) __nv_bfloat16 g_QKVh[(size_t)MROWS*QKVN];  /* V region = fp16 bits */
__device__ __align__(256) __nv_bfloat16 g_QKVl[(size_t)MROWS*QKVN];
__device__ __align__(256) __half        g_At [(size_t)MROWS*EMB];

// ---------------- helpers ----------------
__device__ __forceinline__ uint32_t cvta_smem(const void* p) {
    uint32_t a;
    asm("{ .reg .u64 t; cvta.to.shared.u64 t, %1; cvt.u32.u64 %0, t; }" : "=r"(a) : "l"(p));
    return a;
}
__device__ __forceinline__ void cp16(uint32_t dst, const void* src) {
    asm volatile("cp.async.cg.shared.global [%0], [%1], 16;" :: "r"(dst), "l"(src));
}
#define CP_COMMIT() asm volatile("cp.async.commit_group;" ::: "memory")
#define CP_WAIT2()  asm volatile("cp.async.wait_group 2;" ::: "memory")
#define CP_WAIT1()  asm volatile("cp.async.wait_group 1;" ::: "memory")
#define CP_WAIT0()  asm volatile("cp.async.wait_group 0;" ::: "memory")

__device__ __forceinline__ void ldsm4(uint32_t& r0, uint32_t& r1, uint32_t& r2, uint32_t& r3,
                                      uint32_t addr) {
    asm volatile("ldmatrix.sync.aligned.m8n8.x4.shared.b16 {%0,%1,%2,%3},[%4];"
                 : "=r"(r0), "=r"(r1), "=r"(r2), "=r"(r3) : "r"(addr));
}
__device__ __forceinline__ void ldsm4t(uint32_t& r0, uint32_t& r1, uint32_t& r2, uint32_t& r3,
                                       uint32_t addr) {
    asm volatile("ldmatrix.sync.aligned.m8n8.x4.trans.shared.b16 {%0,%1,%2,%3},[%4];"
                 : "=r"(r0), "=r"(r1), "=r"(r2), "=r"(r3) : "r"(addr));
}
__device__ __forceinline__ void mma_bf(float c[4], const uint32_t a[4], uint32_t b0, uint32_t b1) {
    asm("mma.sync.aligned.m16n8k16.row.col.f32.bf16.bf16.f32 "
        "{%0,%1,%2,%3}, {%4,%5,%6,%7}, {%8,%9}, {%0,%1,%2,%3};"
        : "+f"(c[0]), "+f"(c[1]), "+f"(c[2]), "+f"(c[3])
        : "r"(a[0]), "r"(a[1]), "r"(a[2]), "r"(a[3]), "r"(b0), "r"(b1));
}
__device__ __forceinline__ void mma_hf(float c[4], const uint32_t a[4], uint32_t b0, uint32_t b1) {
    asm("mma.sync.aligned.m16n8k16.row.col.f32.f16.f16.f32 "
        "{%0,%1,%2,%3}, {%4,%5,%6,%7}, {%8,%9}, {%0,%1,%2,%3};"
        : "+f"(c[0]), "+f"(c[1]), "+f"(c[2]), "+f"(c[3])
        : "r"(a[0]), "r"(a[1]), "r"(a[2]), "r"(a[3]), "r"(b0), "r"(b1));
}
__device__ __forceinline__ float ex2(float x) {
    float r;
    asm("ex2.approx.ftz.f32 %0, %1;" : "=f"(r) : "f"(x));
    return r;
}
__device__ __forceinline__ uint32_t ex2_h2(float x, float y) {
    uint32_t h, r;
    asm("cvt.rn.f16x2.f32 %0, %1, %2;" : "=r"(h) : "f"(y), "f"(x));
    asm("ex2.approx.f16x2 %0, %1;" : "=r"(r) : "r"(h));
    return r;
}
__device__ __forceinline__ uint32_t packbf(float x, float y) {
    __nv_bfloat162 t = __floats2bfloat162_rn(x, y);
    return *reinterpret_cast<uint32_t*>(&t);
}
__device__ __forceinline__ uint32_t packres(float x, float y, uint32_t h) {
    __nv_bfloat162 hh = *reinterpret_cast<__nv_bfloat162*>(&h);
    return packbf(x - __bfloat162float(hh.x), y - __bfloat162float(hh.y));
}
__device__ __forceinline__ uint32_t packh(float x, float y) {
    __half2 t = __floats2half2_rn(x, y);
    return *reinterpret_cast<uint32_t*>(&t);
}
__device__ __forceinline__ void split2(float v, __nv_bfloat16& hi, __nv_bfloat16& lo) {
    hi = __float2bfloat16(v);
    lo = __float2bfloat16(v - __bfloat162float(hi));
}

// ---------------- packing kernels ----------------
__global__ void split_x(const float* __restrict__ x, __nv_bfloat16* __restrict__ hi,
                        __nv_bfloat16* __restrict__ lo, __half* __restrict__ hf, int n) {
    int i = blockIdx.x * blockDim.x + threadIdx.x;
    if (i >= n) return;
    float v = x[i];
    split2(v, hi[i], lo[i]);
    hf[i] = __float2half(v);
}

__global__ void pack_qkv_t(const float* __restrict__ Wq, const float* __restrict__ Wk,
                           const float* __restrict__ Wv,
                           __nv_bfloat16* __restrict__ hi, __nv_bfloat16* __restrict__ lo,
                           __half* __restrict__ vf) {
    __shared__ float ts[64][65];
    const int tid = threadIdx.x;
    const int kb = blockIdx.x, hid = blockIdx.y, wh = blockIdx.z;
    const float* src = (wh == 0) ? Wq : (wh == 1) ? Wk : Wv;
    const float sc = (wh == 0) ? QSCALE2 : 1.0f;

#pragma unroll
    for (int p = 0; p < 16; p++) {
        int kr = (tid >> 6) + p * 4;
        int i  = tid & 63;
        ts[kr][i] = src[(size_t)hid * (EMB * HDIM) + (size_t)(kb * 64 + kr) * HDIM + i];
    }
    __syncthreads();
#pragma unroll
    for (int p = 0; p < 16; p++) {
        int i = (tid >> 6) + p * 4;
        int k = tid & 63;
        float v = ts[k][i] * sc;
        if (wh == 2) {
            size_t o = ((size_t)(hid * 64 + i) << 10) + kb * 64 + k;
            vf[o] = __float2half(v);
        } else {
            size_t o = ((size_t)(wh * 1024 + hid * 64 + i) << 10) + kb * 64 + k;
            split2(v, hi[o], lo[o]);
        }
    }
}

__global__ void pack_wo(const float* __restrict__ Wo, __half* __restrict__ hf) {
    int idx = blockIdx.x * blockDim.x + threadIdx.x;
    if (idx >= EMB * EMB) return;
    hf[idx] = __float2half(Wo[idx]);
}

// ---------------- merged projection: QK (bf16 3-pass) + V (fp16 1-pass) ----------------
#define GTILE  8192
#define GSTAGE 32768
#define GVSTAGE 16384
#define GNC    (KDIM/32)

__global__ __launch_bounds__(256, 2)
void gemm_proj(const __nv_bfloat16* __restrict__ Ah, const __nv_bfloat16* __restrict__ Al,
               const __nv_bfloat16* __restrict__ Bh, const __nv_bfloat16* __restrict__ Bl,
               __nv_bfloat16* __restrict__ Ch, __nv_bfloat16* __restrict__ Cl,
               const __half* __restrict__ Af, const __half* __restrict__ Bvf,
               __half* __restrict__ Cv) {
    extern __shared__ __align__(16) char smraw[];
    uint32_t smb = cvta_smem(smraw);
    const int tid = threadIdx.x, lane = tid & 31, wid = tid >> 5;
    const int wm = wid & 3, wn = wid >> 2;
    const int mb = blockIdx.y;
    const int grp = lane >> 2, qr = lane & 3;

    float acc[2][8][4];
#pragma unroll
    for (int a = 0; a < 2; a++)
#pragma unroll
        for (int b = 0; b < 8; b++)
#pragma unroll
            for (int c = 0; c < 4; c++) acc[a][b][c] = 0.f;

    if (blockIdx.x < 16) {
        // ---------- QK path: bf16 3-pass, 3-stage ----------
        const int nb = blockIdx.x;
        const __nv_bfloat16* gsrc[4] = {
            Ah + (size_t)mb * 128 * KDIM, Al + (size_t)mb * 128 * KDIM,
            Bh + (size_t)nb * 128 * KDIM, Bl + (size_t)nb * 128 * KDIM };

        auto ldchunk = [&](int buf, int ck) {
            uint32_t bb = smb + buf * GSTAGE;
#pragma unroll
            for (int q = 0; q < 8; q++) {
                int i = q * 256 + tid;
                int t = i >> 9;
                int r = (i >> 2) & 127;
                int c16 = i & 3;
                uint32_t dst = bb + t * GTILE + r * 64 + ((c16 ^ ((r >> 1) & 3)) << 4);
                cp16(dst, gsrc[t] + (size_t)r * KDIM + ck * 32 + c16 * 8);
            }
        };

        ldchunk(0, 0); CP_COMMIT();
        ldchunk(1, 1); CP_COMMIT();

        int buf = 0, rb = 2;
        for (int c = 0; c < GNC; c++) {
            if (c + 1 < GNC) CP_WAIT1(); else CP_WAIT0();
            __syncthreads();
            if (c + 2 < GNC) {
                ldchunk(rb, c + 2); CP_COMMIT();
                rb = (rb == 2) ? 0 : rb + 1;
            }
            uint32_t bb = smb + buf * GSTAGE;

#pragma unroll
            for (int s = 0; s < 2; s++) {
                uint32_t ah[2][4], al[2][4];
#pragma unroll
                for (int mt = 0; mt < 2; mt++) {
                    uint32_t row = 32 * wm + 16 * mt + ((lane >> 3) & 1) * 8 + (lane & 7);
                    uint32_t kb  = (lane >> 4) * 16 + s * 32;
                    uint32_t ad  = bb + row * 64 + ((((kb >> 4)) ^ ((row >> 1) & 3)) << 4);
                    ldsm4(ah[mt][0], ah[mt][1], ah[mt][2], ah[mt][3], ad);
                    ldsm4(al[mt][0], al[mt][1], al[mt][2], al[mt][3], ad + GTILE);
                }
#pragma unroll
                for (int np = 0; np < 4; np++) {
                    uint32_t row = 64 * wn + 16 * np + ((lane >> 4) & 1) * 8 + (lane & 7);
                    uint32_t kb  = ((lane >> 3) & 1) * 16 + s * 32;
                    uint32_t bd  = bb + 2 * GTILE + row * 64 + ((((kb >> 4)) ^ ((row >> 1) & 3)) << 4);
                    uint32_t bh0, bh1, bh2, bh3, bl0, bl1, bl2, bl3;
                    ldsm4(bh0, bh1, bh2, bh3, bd);
                    ldsm4(bl0, bl1, bl2, bl3, bd + GTILE);
#pragma unroll
                    for (int p = 0; p < 3; p++) {
                        const uint32_t* a0 = (p == 1) ? al[0] : ah[0];
                        const uint32_t* a1 = (p == 1) ? al[1] : ah[1];
                        uint32_t c0 = (p == 2) ? bl0 : bh0, c1 = (p == 2) ? bl1 : bh1;
                        uint32_t c2 = (p == 2) ? bl2 : bh2, c3 = (p == 2) ? bl3 : bh3;
                        mma_bf(acc[0][2 * np],     a0, c0, c1);
                        mma_bf(acc[1][2 * np],     a1, c0, c1);
                        mma_bf(acc[0][2 * np + 1], a0, c2, c3);
                        mma_bf(acc[1][2 * np + 1], a1, c2, c3);
                    }
                }
            }
            buf = (buf == 2) ? 0 : buf + 1;
        }

#pragma unroll
        for (int mt = 0; mt < 2; mt++) {
            size_t r0 = (size_t)mb * 128 + 32 * wm + 16 * mt + grp;
#pragma unroll
            for (int nt = 0; nt < 8; nt++) {
                int col = nb * 128 + 64 * wn + 8 * nt + 2 * qr;
                float* c4 = acc[mt][nt];
                uint32_t h0 = packbf(c4[0], c4[1]), l0 = packres(c4[0], c4[1], h0);
                uint32_t h1 = packbf(c4[2], c4[3]), l1 = packres(c4[2], c4[3], h1);
                *(uint32_t*)&Ch[r0 * QKVN + col]       = h0;
                *(uint32_t*)&Cl[r0 * QKVN + col]       = l0;
                *(uint32_t*)&Ch[(r0 + 8) * QKVN + col] = h1;
                *(uint32_t*)&Cl[(r0 + 8) * QKVN + col] = l1;
            }
        }
    } else {
        // ---------- V path: fp16 1-pass, 4-stage ----------
        const int nb = blockIdx.x - 16;
        const __half* gsrc[2] = { Af + (size_t)mb * 128 * KDIM, Bvf + (size_t)nb * 128 * KDIM };

        auto ldchunk = [&](int buf, int ck) {
            uint32_t bb = smb + buf * GVSTAGE;
#pragma unroll
            for (int q = 0; q < 4; q++) {
                int i = q * 256 + tid;
                int t = i >> 9;
                int r = (i >> 2) & 127;
                int c16 = i & 3;
                uint32_t dst = bb + t * GTILE + r * 64 + ((c16 ^ ((r >> 1) & 3)) << 4);
                cp16(dst, gsrc[t] + (size_t)r * KDIM + ck * 32 + c16 * 8);
            }
        };

        ldchunk(0, 0); CP_COMMIT();
        ldchunk(1, 1); CP_COMMIT();
        ldchunk(2, 2); CP_COMMIT();

        int rb = 3;
        for (int c = 0; c < GNC; c++) {
            int rem = GNC - c;
            if (rem >= 3) CP_WAIT2(); else if (rem == 2) CP_WAIT1(); else CP_WAIT0();
            __syncthreads();
            if (c + 3 < GNC) {
                ldchunk(rb, c + 3); CP_COMMIT();
                rb = (rb + 1) & 3;
            }
            uint32_t bb = smb + (c & 3) * GVSTAGE;

#pragma unroll
            for (int s = 0; s < 2; s++) {
                uint32_t ah[2][4];
#pragma unroll
                for (int mt = 0; mt < 2; mt++) {
                    uint32_t row = 32 * wm + 16 * mt + ((lane >> 3) & 1) * 8 + (lane & 7);
                    uint32_t kb  = (lane >> 4) * 16 + s * 32;
                    uint32_t ad  = bb + row * 64 + ((((kb >> 4)) ^ ((row >> 1) & 3)) << 4);
                    ldsm4(ah[mt][0], ah[mt][1], ah[mt][2], ah[mt][3], ad);
                }
#pragma unroll
                for (int np = 0; np < 4; np++) {
                    uint32_t row = 64 * wn + 16 * np + ((lane >> 4) & 1) * 8 + (lane & 7);
                    uint32_t kb  = ((lane >> 3) & 1) * 16 + s * 32;
                    uint32_t bd  = bb + GTILE + row * 64 + ((((kb >> 4)) ^ ((row >> 1) & 3)) << 4);
                    uint32_t b0, b1, b2, b3;
                    ldsm4(b0, b1, b2, b3, bd);
                    mma_hf(acc[0][2 * np],     ah[0], b0, b1);
                    mma_hf(acc[1][2 * np],     ah[1], b0, b1);
                    mma_hf(acc[0][2 * np + 1], ah[0], b2, b3);
                    mma_hf(acc[1][2 * np + 1], ah[1], b2, b3);
                }
            }
        }

#pragma unroll
        for (int mt = 0; mt < 2; mt++) {
            size_t r0 = (size_t)mb * 128 + 32 * wm + 16 * mt + grp;
#pragma unroll
            for (int nt = 0; nt < 8; nt++) {
                int col = nb * 128 + 64 * wn + 8 * nt + 2 * qr;
                float* c4 = acc[mt][nt];
                *(uint32_t*)&Cv[r0 * QKVN + col]       = packh(c4[0], c4[1]);
                *(uint32_t*)&Cv[(r0 + 8) * QKVN + col] = packh(c4[2], c4[3]);
            }
        }
    }
}

// ---------------- GEMM-O: fp16 1-pass, 4-stage ----------------
#define GOSTAGE 16384

__global__ __launch_bounds__(256, 2)
void gemm_o(const __half* __restrict__ A, const __half* __restrict__ B,
            float* __restrict__ C, int N) {
    extern __shared__ __align__(16) char smraw[];
    uint32_t smb = cvta_smem(smraw);
    const int tid = threadIdx.x, lane = tid & 31, wid = tid >> 5;
    const int wm = wid & 3, wn = wid >> 2;
    const int nb = blockIdx.x, mb = blockIdx.y;

    const __half* gsrc[2] = { A + (size_t)mb * 128 * KDIM, B + (size_t)nb * 128 * KDIM };

    auto ldchunk = [&](int buf, int ck) {
        uint32_t bb = smb + buf * GOSTAGE;
#pragma unroll
        for (int q = 0; q < 4; q++) {
            int i = q * 256 + tid;
            int t = i >> 9;
            int r = (i >> 2) & 127;
            int c16 = i & 3;
            uint32_t dst = bb + t * GTILE + r * 64 + ((c16 ^ ((r >> 1) & 3)) << 4);
            cp16(dst, gsrc[t] + (size_t)r * KDIM + ck * 32 + c16 * 8);
        }
    };

    ldchunk(0, 0); CP_COMMIT();
    ldchunk(1, 1); CP_COMMIT();
    ldchunk(2, 2); CP_COMMIT();

    float acc[2][8][4];
#pragma unroll
    for (int a = 0; a < 2; a++)
#pragma unroll
        for (int b = 0; b < 8; b++)
#pragma unroll
            for (int c = 0; c < 4; c++) acc[a][b][c] = 0.f;

    int rb = 3;
    for (int c = 0; c < GNC; c++) {
        int rem = GNC - c;
        if (rem >= 3) CP_WAIT2(); else if (rem == 2) CP_WAIT1(); else CP_WAIT0();
        __syncthreads();
        if (c + 3 < GNC) {
            ldchunk(rb, c + 3); CP_COMMIT();
            rb = (rb + 1) & 3;
        }
        uint32_t bb = smb + (c & 3) * GOSTAGE;

#pragma unroll
        for (int s = 0; s < 2; s++) {
            uint32_t ah[2][4];
#pragma unroll
            for (int mt = 0; mt < 2; mt++) {
                uint32_t row = 32 * wm + 16 * mt + ((lane >> 3) & 1) * 8 + (lane & 7);
                uint32_t kb  = (lane >> 4) * 16 + s * 32;
                uint32_t ad  = bb + row * 64 + ((((kb >> 4)) ^ ((row >> 1) & 3)) << 4);
                ldsm4(ah[mt][0], ah[mt][1], ah[mt][2], ah[mt][3], ad);
            }
#pragma unroll
            for (int np = 0; np < 4; np++) {
                uint32_t row = 64 * wn + 16 * np + ((lane >> 4) & 1) * 8 + (lane & 7);
                uint32_t kb  = ((lane >> 3) & 1) * 16 + s * 32;
                uint32_t bd  = bb + GTILE + row * 64 + ((((kb >> 4)) ^ ((row >> 1) & 3)) << 4);
                uint32_t b0, b1, b2, b3;
                ldsm4(b0, b1, b2, b3, bd);
                mma_hf(acc[0][2 * np],     ah[0], b0, b1);
                mma_hf(acc[1][2 * np],     ah[1], b0, b1);
                mma_hf(acc[0][2 * np + 1], ah[0], b2, b3);
                mma_hf(acc[1][2 * np + 1], ah[1], b2, b3);
            }
        }
    }

    const int grp = lane >> 2, qr = lane & 3;
#pragma unroll
    for (int mt = 0; mt < 2; mt++) {
        size_t r0 = (size_t)mb * 128 + 32 * wm + 16 * mt + grp;
#pragma unroll
        for (int nt = 0; nt < 8; nt++) {
            int col = nb * 128 + 64 * wn + 8 * nt + 2 * qr;
            float* c4 = acc[mt][nt];
            *(float2*)&C[r0 * N + col]       = make_float2(c4[0], c4[1]);
            *(float2*)&C[(r0 + 8) * N + col] = make_float2(c4[2], c4[3]);
        }
    }
}

// ---------------- Flash attention: fp16x2 softmax + MMA l-sum + PV ldsm pipelining ----------------
#define FPITCH 144
#define FTILE  9216
#define FSTAGE 27648
#define NKT    (SEQ/64)
#define ONES2  0x3C003C00u

__global__ __launch_bounds__(256, 2)
void flash_mma(const __nv_bfloat16* __restrict__ Qh, const __nv_bfloat16* __restrict__ Ql,
               __half* __restrict__ Out) {
    extern __shared__ __align__(16) char smraw[];
    uint32_t smb = cvta_smem(smraw);

    const int tid = threadIdx.x, lane = tid & 31, w = tid >> 5;
    const int grp = lane >> 2, qr = lane & 3;
    const int qt = blockIdx.x, h = blockIdx.y, b = blockIdx.z;

    const size_t batch_row = (size_t)b * SEQ;

    const __nv_bfloat16* kvsrc[3] = {
        Qh + batch_row * QKVN + EMB + h * HDIM,
        Ql + batch_row * QKVN + EMB + h * HDIM,
        Qh + batch_row * QKVN + 2 * EMB + h * HDIM };

    auto ldtile = [&](int bf, int kt) {
        uint32_t bb = smb + bf * FSTAGE;
        size_t rbase = (size_t)kt * 64;
#pragma unroll
        for (int q = 0; q < 6; q++) {
            int i = q * 256 + tid;
            int t = i >> 9;
            int r = (i >> 3) & 63;
            int sg = i & 7;
            cp16(bb + t * FTILE + r * FPITCH + sg * 16,
                 kvsrc[t] + (rbase + r) * QKVN + sg * 8);
        }
    };

    uint32_t qh[4][4], ql[4][4];
    {
        size_t r0 = batch_row + (size_t)qt * 128 + w * 16 + grp;
        const __nv_bfloat16* qb_h = Qh + r0 * QKVN + h * HDIM;
        const __nv_bfloat16* qb_l = Ql + r0 * QKVN + h * HDIM;
#pragma unroll
        for (int t = 0; t < 4; t++) {
            int c0 = t * 16 + 2 * qr;
            qh[t][0] = *(const uint32_t*)(qb_h + c0);
            qh[t][1] = *(const uint32_t*)(qb_h + 8 * QKVN + c0);
            qh[t][2] = *(const uint32_t*)(qb_h + c0 + 8);
            qh[t][3] = *(const uint32_t*)(qb_h + 8 * QKVN + c0 + 8);
            ql[t][0] = *(const uint32_t*)(qb_l + c0);
            ql[t][1] = *(const uint32_t*)(qb_l + 8 * QKVN + c0);
            ql[t][2] = *(const uint32_t*)(qb_l + c0 + 8);
            ql[t][3] = *(const uint32_t*)(qb_l + 8 * QKVN + c0 + 8);
        }
    }

    float o[8][4];
#pragma unroll
    for (int j = 0; j < 8; j++)
#pragma unroll
        for (int c = 0; c < 4; c++) o[j][c] = 0.f;
    float lacc[4] = {0.f, 0.f, 0.f, 0.f};
    float m0 = -1e30f, m1 = -1e30f;

    ldtile(0, 0); CP_COMMIT();
    ldtile(1, 1); CP_COMMIT();
    ldtile(2, 2); CP_COMMIT();

    int rb = 3;
    for (int kt = 0; kt < NKT; kt++) {
        int rem = NKT - kt;
        if (rem >= 3) CP_WAIT2(); else if (rem == 2) CP_WAIT1(); else CP_WAIT0();
        __syncthreads();
        if (kt + 3 < NKT) {
            ldtile(rb, kt + 3); CP_COMMIT();
            rb = (rb + 1) & 3;
        }
        uint32_t sb  = smb + (kt & 3) * FSTAGE;
        uint32_t khb = sb, vhb = sb + 2 * FTILE;

        // ---- S = Q K^T (16 x 64 per warp), bf16 3-pass ----
        float s[8][4];
#pragma unroll
        for (int j = 0; j < 8; j++) {
            uint32_t ka = khb + (8 * j + (lane & 7)) * FPITCH + (lane >> 3) * 16;
            uint32_t la = ka + FTILE;
            uint32_t h0, h1, h2, h3, h4, h5, h6, h7;
            uint32_t e0, e1, e2, e3, e4, e5, e6, e7;
            ldsm4(h0, h1, h2, h3, ka);
            ldsm4(h4, h5, h6, h7, ka + 64);
            ldsm4(e0, e1, e2, e3, la);
            ldsm4(e4, e5, e6, e7, la + 64);
            s[j][0] = s[j][1] = s[j][2] = s[j][3] = 0.f;
            mma_bf(s[j], qh[0], h0, h1); mma_bf(s[j], ql[0], h0, h1); mma_bf(s[j], qh[0], e0, e1);
            mma_bf(s[j], qh[1], h2, h3); mma_bf(s[j], ql[1], h2, h3); mma_bf(s[j], qh[1], e2, e3);
            mma_bf(s[j], qh[2], h4, h5); mma_bf(s[j], ql[2], h4, h5); mma_bf(s[j], qh[2], e4, e5);
            mma_bf(s[j], qh[3], h6, h7); mma_bf(s[j], ql[3], h6, h7); mma_bf(s[j], qh[3], e6, e7);
        }

        // ---- prefetch first V fragments (LDS latency hides under softmax) ----
        const uint32_t va0 = vhb + lane * FPITCH;          // kcp = 0 rows
        const uint32_t va1 = vhb + (32 + lane) * FPITCH;   // kcp = 1 rows
        uint32_t vp[2][4];
        ldsm4t(vp[0][0], vp[0][1], vp[0][2], vp[0][3], va0);
        ldsm4t(vp[1][0], vp[1][1], vp[1][2], vp[1][3], va0 + 16);

        // ---- maxima (quad-reduced) ----
        float t0 = -1e30f, t1 = -1e30f;
#pragma unroll
        for (int j = 0; j < 8; j++) {
            t0 = fmaxf(t0, fmaxf(s[j][0], s[j][1]));
            t1 = fmaxf(t1, fmaxf(s[j][2], s[j][3]));
        }
        t0 = fmaxf(t0, __shfl_xor_sync(0xffffffffu, t0, 1));
        t0 = fmaxf(t0, __shfl_xor_sync(0xffffffffu, t0, 2));
        t1 = fmaxf(t1, __shfl_xor_sync(0xffffffffu, t1, 1));
        t1 = fmaxf(t1, __shfl_xor_sync(0xffffffffu, t1, 2));

        bool negl = (t0 < m0 - SKIP_T) && (t1 < m1 - SKIP_T);
        if (__all_sync(0xffffffffu, negl)) continue;

        bool newmax = (t0 > m0) || (t1 > m1);
        if (newmax) {
            float n0 = fmaxf(m0, t0), n1 = fmaxf(m1, t1);
            float a0 = ex2(m0 - n0), a1 = ex2(m1 - n1);
            lacc[0] *= a0; lacc[1] *= a0; lacc[2] *= a1; lacc[3] *= a1;
#pragma unroll
            for (int j = 0; j < 8; j++) {
                o[j][0] *= a0; o[j][1] *= a0; o[j][2] *= a1; o[j][3] *= a1;
            }
            m0 = n0; m1 = n1;
        }

        // ---- P = exp2(s - m) in fp16x2, as MMA A-fragments ----
        uint32_t pf[4][4];
#pragma unroll
        for (int f = 0; f < 4; f++) {
            int j0 = 2 * f, j1 = 2 * f + 1;
            pf[f][0] = ex2_h2(s[j0][0] - m0, s[j0][1] - m0);
            pf[f][1] = ex2_h2(s[j0][2] - m1, s[j0][3] - m1);
            pf[f][2] = ex2_h2(s[j1][0] - m0, s[j1][1] - m0);
            pf[f][3] = ex2_h2(s[j1][2] - m1, s[j1][3] - m1);
        }

        // ---- l += P · 1 ----
        mma_hf(lacc, pf[0], ONES2, ONES2);
        mma_hf(lacc, pf[1], ONES2, ONES2);
        mma_hf(lacc, pf[2], ONES2, ONES2);
        mma_hf(lacc, pf[3], ONES2, ONES2);

        // ---- O += P V : fp16 single-pass, distance-2 ldsm pipeline ----
#pragma unroll
        for (int kcp = 0; kcp < 2; kcp++) {
            uint32_t va = kcp ? va1 : va0;
#pragma unroll
            for (int j2 = 0; j2 < 8; j2++) {
                uint32_t c0 = vp[j2 & 1][0], c1 = vp[j2 & 1][1];
                uint32_t c2 = vp[j2 & 1][2], c3 = vp[j2 & 1][3];
                // prefetch fragment j2+2 (same kcp) or roll into next kcp
                if (j2 < 6) {
                    ldsm4t(vp[j2 & 1][0], vp[j2 & 1][1], vp[j2 & 1][2], vp[j2 & 1][3],
                           va + (j2 + 2) * 16);
                } else if (kcp == 0) {
                    ldsm4t(vp[j2 & 1][0], vp[j2 & 1][1], vp[j2 & 1][2], vp[j2 & 1][3],
                           va1 + (j2 - 6) * 16);
                }
                mma_hf(o[j2], pf[2 * kcp],     c0, c1);
                mma_hf(o[j2], pf[2 * kcp + 1], c2, c3);
            }
        }
    }

    // ---- epilogue ----
    float inv0 = 1.f / lacc[0], inv1 = 1.f / lacc[2];
    size_t r0 = batch_row + (size_t)qt * 128 + w * 16 + grp;
#pragma unroll
    for (int j2 = 0; j2 < 8; j2++) {
        int c = h * HDIM + 8 * j2 + 2 * qr;
        *(uint32_t*)&Out[r0 * EMB + c]       = packh(o[j2][0] * inv0, o[j2][1] * inv0);
        *(uint32_t*)&Out[(r0 + 8) * EMB + c] = packh(o[j2][2] * inv1, o[j2][3] * inv1);
    }
}

// ------------------------------------------------------------------
extern "C" void kernel_launch(void* const* d_in, const int* in_sizes, int n_in,
                              void* d_out, int out_size) {
    const float* x  = (const float*)d_in[0];
    const float* Wq = (const float*)d_in[1];
    const float* Wk = (const float*)d_in[2];
    const float* Wv = (const float*)d_in[3];
    const float* Wo = (const float*)d_in[4];
    float* out = (float*)d_out;

    __nv_bfloat16 *gxh, *gxl, *gBqh, *gBql, *gQh, *gQl;
    __half *gxf, *gBvf, *gBof, *gAt;
    cudaGetSymbolAddress((void**)&gxh,  g_xh);
    cudaGetSymbolAddress((void**)&gxl,  g_xl);
    cudaGetSymbolAddress((void**)&gxf,  g_xf);
    cudaGetSymbolAddress((void**)&gBqh, g_Bqh);
    cudaGetSymbolAddress((void**)&gBql, g_Bql);
    cudaGetSymbolAddress((void**)&gBvf, g_Bvf);
    cudaGetSymbolAddress((void**)&gBof, g_Bof);
    cudaGetSymbolAddress((void**)&gQh,  g_QKVh);
    cudaGetSymbolAddress((void**)&gQl,  g_QKVl);
    cudaGetSymbolAddress((void**)&gAt,  g_At);

    const int GPSMEM = 3 * GSTAGE;     // 98304
    const int GOSMEM = 4 * GOSTAGE;    // 65536
    const int FSMEM  = 4 * FSTAGE;     // 110592
    cudaFuncSetAttribute(gemm_proj, cudaFuncAttributeMaxDynamicSharedMemorySize, GPSMEM);
    cudaFuncSetAttribute(gemm_o,    cudaFuncAttributeMaxDynamicSharedMemorySize, GOSMEM);
    cudaFuncSetAttribute(flash_mma, cudaFuncAttributeMaxDynamicSharedMemorySize, FSMEM);

    split_x<<<(MROWS * EMB + 255) / 256, 256>>>(x, gxh, gxl, gxf, MROWS * EMB);
    pack_qkv_t<<<dim3(16, 16, 3), 256>>>(Wq, Wk, Wv, gBqh, gBql, gBvf);
    pack_wo<<<(EMB * EMB + 255) / 256, 256>>>(Wo, gBof);

    gemm_proj<<<dim3(24, MROWS / 128), 256, GPSMEM>>>(
        gxh, gxl, gBqh, gBql, gQh, gQl,
        gxf, gBvf, reinterpret_cast<__half*>(gQh) + 2 * EMB);

    flash_mma<<<dim3(SEQ / 128, HEADS, BATCH), 256, FSMEM>>>(gQh, gQl, gAt);

    gemm_o<<<dim3(EMB / 128, MROWS / 128), 256, GOSMEM>>>(gAt, gBof, out, EMB);
}